// round 6
// baseline (speedup 1.0000x reference)
#include <cuda_runtime.h>
#include <stdint.h>

// Problem constants (fixed shapes from reference):
//   embeddings: [B=32, L=4, W=512, D=768] float32
//   segment_ids: [B=32, W=512] int32, sorted per row, values in [0, W)
// Outputs (concatenated into d_out, float32, return order):
//   word_embeds [B, D, W]  (B*D*W = 12,582,912 floats)
//   sent_embeds [B, D]     (B*D   =     24,576 floats)
//
// word[b,d,s] = (1/L) * sum_{w: seg[b,w]==s} sum_l emb[b,l,w,d]
// sent[b,d]   = (1/W) * sum_s word[b,d,s]
//
// segment ids are SORTED per row -> each segment s occupies a contiguous
// w-run. The segment_sum scatter therefore becomes a gather over disjoint
// runs: every embedding element is read exactly once, no atomics on the
// word output, and unused word slots are zero-filled for free by zeroing
// the smem tile.

#define BB 32
#define LL 4
#define WW 512
#define DD 768

#define TILE_S 64    // segments per block (output W-tile)
#define TILE_D 128   // d-channels per block (== blockDim.x)
#define NTHR   128

__global__ void zero_sent_kernel(float* __restrict__ sent) {
    int i = blockIdx.x * blockDim.x + threadIdx.x;
    if (i < BB * DD) sent[i] = 0.0f;
}

__device__ __forceinline__ int lower_bound_smem(const int* a, int n, int v) {
    int lo = 0, hi = n;
    while (lo < hi) {
        int m = (lo + hi) >> 1;
        if (a[m] < v) lo = m + 1; else hi = m;
    }
    return lo;
}

__global__ __launch_bounds__(NTHR)
void word_agg_kernel(const float* __restrict__ emb,
                     const int*   __restrict__ seg,
                     float*       __restrict__ word,   // [B, D, W]
                     float*       __restrict__ sent)   // [B, D]
{
    // +1 pad -> row stride 129 (odd) : conflict-free for both the
    // d-major run-flush stores and the s-major transposed reads.
    __shared__ float tile[TILE_S][TILE_D + 1];
    __shared__ int   segs[WW];

    const int b   = blockIdx.z;
    const int s0  = blockIdx.y * TILE_S;
    const int d0  = blockIdx.x * TILE_D;
    const int tid = threadIdx.x;

    // Cache this row's segment ids.
    #pragma unroll
    for (int i = tid; i < WW; i += NTHR) segs[i] = seg[b * WW + i];

    // Zero the accumulation tile (empty segments must output 0).
    #pragma unroll
    for (int i = tid; i < TILE_S * TILE_D; i += NTHR)
        tile[i / TILE_D][i % TILE_D] = 0.0f;

    __syncthreads();

    // w-range whose segment ids fall in [s0, s0+TILE_S). All threads
    // compute the same bounds from smem (broadcast reads).
    const int wlo = lower_bound_smem(segs, WW, s0);
    const int whi = lower_bound_smem(segs, WW, s0 + TILE_S);

    const int d = d0 + tid;
    const float* __restrict__ base = emb + ((size_t)b * LL * WW) * DD + d;
    const size_t LSTRIDE = (size_t)WW * DD;   // layer stride in floats

    // Serial run-accumulation: each thread owns column d, so run flushes
    // are plain smem stores (no atomics). seg sequence is uniform across
    // the block -> no divergence.
    float acc = 0.0f;
    int   cur = -1;
    for (int w = wlo; w < whi; ++w) {
        const int s = segs[w];
        if (s != cur) {
            if (cur >= 0) tile[cur - s0][tid] = acc;
            acc = 0.0f;
            cur = s;
        }
        const float* p = base + (size_t)w * DD;
        float e0 = __ldg(p);
        float e1 = __ldg(p + LSTRIDE);
        float e2 = __ldg(p + 2 * LSTRIDE);
        float e3 = __ldg(p + 3 * LSTRIDE);
        acc += (e0 + e1) + (e2 + e3);
    }
    if (cur >= 0) tile[cur - s0][tid] = acc;

    __syncthreads();

    // sent contribution: column sum over this s-tile for each d.
    // (sent = (1/W) * sum_s word[b,d,s];  word = 0.25 * acc)
    {
        float colsum = 0.0f;
        #pragma unroll
        for (int s = 0; s < TILE_S; ++s) colsum += tile[s][tid];
        atomicAdd(&sent[b * DD + d], colsum * (0.25f / (float)WW));
    }

    // Transposed, fully coalesced write: word[b, d0+dd, s0+ss].
    // tid-consecutive -> ss fastest -> 256B contiguous stores per half-warp
    // group; smem read addr ss*129+dd -> conflict-free.
    float* __restrict__ outb = word + ((size_t)b * DD + d0) * WW + s0;
    #pragma unroll
    for (int i = tid; i < TILE_S * TILE_D; i += NTHR) {
        const int dd = i / TILE_S;
        const int ss = i % TILE_S;
        outb[(size_t)dd * WW + ss] = 0.25f * tile[ss][dd];
    }
}

extern "C" void kernel_launch(void* const* d_in, const int* in_sizes, int n_in,
                              void* d_out, int out_size) {
    const float* emb = (const float*)d_in[0];
    const int*   seg = (const int*)d_in[1];

    float* word = (float*)d_out;                       // [B, D, W]
    float* sent = word + (size_t)BB * DD * WW;         // [B, D]

    zero_sent_kernel<<<(BB * DD + 255) / 256, 256>>>(sent);

    dim3 grid(DD / TILE_D, WW / TILE_S, BB);           // (6, 8, 32) = 1536 blocks
    word_agg_kernel<<<grid, NTHR>>>(emb, seg, word, sent);
}

// round 7
// speedup vs baseline: 1.1173x; 1.1173x over previous
#include <cuda_runtime.h>
#include <stdint.h>

// embeddings: [B=32, L=4, W=512, D=768] f32; segment_ids: [B=32, W=512] i32 sorted/row.
// Out (f32, concat): word [B, D, W] then sent [B, D].
//
// word[b,d,s] = (1/L) * sum_{w: seg[b,w]==s} sum_l emb[b,l,w,d]
// sent[b,d]   = (1/W) * sum_s word[b,d,s]
//
// Sorted segs -> each segment is a contiguous w-run -> pure gather, no scatter
// atomics, each embedding element read exactly once.
//
// R6 change: float4 per thread (4x MLP: 4 LDG.128 in flight per w-iter),
// 96 threads x 4 = 384 d-channels per block, TILE_S=16, smem 27KB -> 8 blocks/SM.

#define BB 32
#define LL 4
#define WW 512
#define DD 768

#define TILE_S 16          // segments per block
#define NTHR   96          // threads per block
#define TILE_D (NTHR * 4)  // 384 d-channels per block (float4/thread)
#define STRIDE 388         // smem row stride in floats (97 f4/row; 97%8==1 -> STS.128 conflict-free)

__global__ void zero_sent_kernel(float* __restrict__ sent) {
    int i = blockIdx.x * blockDim.x + threadIdx.x;
    if (i < BB * DD) sent[i] = 0.0f;
}

__device__ __forceinline__ int lower_bound_smem(const int* a, int n, int v) {
    int lo = 0, hi = n;
    while (lo < hi) {
        int m = (lo + hi) >> 1;
        if (a[m] < v) lo = m + 1; else hi = m;
    }
    return lo;
}

__global__ __launch_bounds__(NTHR)
void word_agg_kernel(const float* __restrict__ emb,
                     const int*   __restrict__ seg,
                     float*       __restrict__ word,   // [B, D, W]
                     float*       __restrict__ sent)   // [B, D]
{
    __shared__ float tile[TILE_S][STRIDE];  // 16 x 388 x 4B = 24,832 B
    __shared__ int   segs[WW];              // 2 KB

    const int b   = blockIdx.z;
    const int s0  = blockIdx.y * TILE_S;
    const int d0  = blockIdx.x * TILE_D;
    const int tid = threadIdx.x;

    // Cache this row's segment ids.
    #pragma unroll
    for (int i = tid; i < WW; i += NTHR) segs[i] = seg[b * WW + i];

    // Zero the accumulation tile (empty segments must output 0), float4-wide.
    {
        float4* t4 = (float4*)&tile[0][0];
        const int n4 = TILE_S * (STRIDE / 4);  // STRIDE%4==0
        const float4 z = make_float4(0.f, 0.f, 0.f, 0.f);
        for (int i = tid; i < n4; i += NTHR) t4[i] = z;
    }
    __syncthreads();

    // w-range whose segment ids fall in [s0, s0+TILE_S).
    const int wlo = lower_bound_smem(segs, WW, s0);
    const int whi = lower_bound_smem(segs, WW, s0 + TILE_S);

    const int d = d0 + tid * 4;
    const float* __restrict__ base = emb + ((size_t)b * LL * WW) * DD + d;
    const size_t LSTRIDE = (size_t)WW * DD;  // layer stride in floats

    // Serial run-accumulation. Each thread owns 4 d-channels; run flush is a
    // single STS.128 (conflict-free). seg sequence uniform across block -> no
    // divergence. 4 independent LDG.128 per iter = 64B in flight per thread.
    float4 acc = make_float4(0.f, 0.f, 0.f, 0.f);
    int    cur = -1;
    for (int w = wlo; w < whi; ++w) {
        const int s = segs[w];
        if (s != cur) {
            if (cur >= 0) ((float4*)&tile[cur - s0][0])[tid] = acc;
            acc = make_float4(0.f, 0.f, 0.f, 0.f);
            cur = s;
        }
        const float* p = base + (size_t)w * DD;
        float4 e0 = *(const float4*)(p);
        float4 e1 = *(const float4*)(p + LSTRIDE);
        float4 e2 = *(const float4*)(p + 2 * LSTRIDE);
        float4 e3 = *(const float4*)(p + 3 * LSTRIDE);
        acc.x += (e0.x + e1.x) + (e2.x + e3.x);
        acc.y += (e0.y + e1.y) + (e2.y + e3.y);
        acc.z += (e0.z + e1.z) + (e2.z + e3.z);
        acc.w += (e0.w + e1.w) + (e2.w + e3.w);
    }
    if (cur >= 0) ((float4*)&tile[cur - s0][0])[tid] = acc;

    __syncthreads();

    // sent contribution: column sum over this s-tile (float4 LDS, conflict-free).
    {
        float4 cs = make_float4(0.f, 0.f, 0.f, 0.f);
        #pragma unroll
        for (int s = 0; s < TILE_S; ++s) {
            float4 v = ((const float4*)&tile[s][0])[tid];
            cs.x += v.x; cs.y += v.y; cs.z += v.z; cs.w += v.w;
        }
        const float k = 0.25f / (float)WW;
        float* sp = sent + b * DD + d;
        atomicAdd(sp + 0, cs.x * k);
        atomicAdd(sp + 1, cs.y * k);
        atomicAdd(sp + 2, cs.z * k);
        atomicAdd(sp + 3, cs.w * k);
    }

    // Transposed coalesced write: word[b, d0+dd, s0 + ss4*4 .. +3] as float4.
    // Per warp: dd 0..7 x ss 0..15 -> 8 contiguous 64B chunks, full sectors.
    float* __restrict__ outb = word + ((size_t)b * DD + d0) * WW + s0;
    const int NOUT = (TILE_S / 4) * TILE_D;  // 1536 float4 stores
    for (int i2 = tid; i2 < NOUT; i2 += NTHR) {
        const int ss4 = i2 & 3;
        const int dd  = i2 >> 2;
        float4 v;
        v.x = 0.25f * tile[ss4 * 4 + 0][dd];
        v.y = 0.25f * tile[ss4 * 4 + 1][dd];
        v.z = 0.25f * tile[ss4 * 4 + 2][dd];
        v.w = 0.25f * tile[ss4 * 4 + 3][dd];
        *(float4*)(outb + (size_t)dd * WW + ss4 * 4) = v;
    }
}

extern "C" void kernel_launch(void* const* d_in, const int* in_sizes, int n_in,
                              void* d_out, int out_size) {
    const float* emb = (const float*)d_in[0];
    const int*   seg = (const int*)d_in[1];

    float* word = (float*)d_out;                   // [B, D, W]
    float* sent = word + (size_t)BB * DD * WW;     // [B, D]

    zero_sent_kernel<<<(BB * DD + 255) / 256, 256>>>(sent);

    dim3 grid(DD / TILE_D, WW / TILE_S, BB);       // (2, 32, 32) = 2048 blocks
    word_agg_kernel<<<grid, NTHR>>>(emb, seg, word, sent);
}